// round 6
// baseline (speedup 1.0000x reference)
#include <cuda_runtime.h>
#include <cuda_bf16.h>
#include <cstdint>
#include <math.h>

#define HDIM 4096
#define NTOK 4096
#define VOC  32000
#define BM   128
#define BN   128
#define BK   64
#define KIT  (HDIM/BK)   // 64
#define NVT  (VOC/BN)    // 250
#define NSTG 3

// ---- dynamic smem layout ----
#define SM_BIAS   0                       // 128 floats
#define SM_RED    512                     // 128x4 floats = 2048
#define SM_TILES  4096
#define STG_BYTES 32768                   // A 16K + B 16K
#define SM_AOFF   0
#define SM_BOFF   16384
#define SMEM_TOTAL (SM_TILES + NSTG*STG_BYTES)   // 102400

// ---- device scratch ----
__device__ __nv_bfloat16 g_Wb[(size_t)VOC*HDIM];   // 262 MB
__device__ __nv_bfloat16 g_Xb[(size_t)NTOK*HDIM];  // 33 MB
__device__ float g_partial[(size_t)NVT*NTOK];      // 4 MB
__device__ float g_tgt[NTOK];
__device__ float g_nll[NTOK];
__device__ int   g_t64;

// ---------------- helpers ----------------
static __device__ __forceinline__ uint32_t s2u(const void* p){
    uint32_t a;
    asm("{ .reg .u64 t; cvta.to.shared.u64 t, %1; cvt.u32.u64 %0, t; }" : "=r"(a) : "l"(p));
    return a;
}
static __device__ __forceinline__ uint32_t swz(uint32_t x){ return x ^ ((x>>3)&0x70u); }

static __device__ __forceinline__ void cp16(uint32_t s, const void* g){
    asm volatile("cp.async.cg.shared.global [%0], [%1], 16;" :: "r"(s), "l"(g));
}
static __device__ __forceinline__ void ldm4(uint32_t* r, uint32_t addr){
    asm volatile("ldmatrix.sync.aligned.m8n8.x4.shared.b16 {%0,%1,%2,%3}, [%4];"
                 : "=r"(r[0]), "=r"(r[1]), "=r"(r[2]), "=r"(r[3]) : "r"(addr));
}
static __device__ __forceinline__ void mma16816(float* c, const uint32_t* a, const uint32_t* b){
    asm volatile("mma.sync.aligned.m16n8k16.row.col.f32.bf16.bf16.f32 "
                 "{%0,%1,%2,%3}, {%4,%5,%6,%7}, {%8,%9}, {%0,%1,%2,%3};"
                 : "+f"(c[0]), "+f"(c[1]), "+f"(c[2]), "+f"(c[3])
                 : "r"(a[0]), "r"(a[1]), "r"(a[2]), "r"(a[3]), "r"(b[0]), "r"(b[1]));
}

// ---------------- fp32 -> bf16 ----------------
__global__ void __launch_bounds__(256) cvt_bf16(const float4* __restrict__ src,
                                                uint2* __restrict__ dst, int nvec){
    int i = blockIdx.x*256 + threadIdx.x;
    if (i >= nvec) return;
    float4 v = src[i];
    union { __nv_bfloat16 h[4]; uint2 u; } o;
    o.h[0] = __float2bfloat16(v.x);
    o.h[1] = __float2bfloat16(v.y);
    o.h[2] = __float2bfloat16(v.z);
    o.h[3] = __float2bfloat16(v.w);
    dst[i] = o.u;
}

// ---------------- target dtype sniffing (int64 vs int32) ----------------
__global__ void detect_t64(const unsigned int* __restrict__ t){
    if (threadIdx.x == 0){
        int ok = 1;
        #pragma unroll
        for (int i = 0; i < 16; i++){
            unsigned lo = t[2*i], hi = t[2*i+1];
            if (!(hi == 0u || (hi == 0xFFFFFFFFu && (lo >> 31)))) ok = 0;
        }
        g_t64 = ok;
    }
}
static __device__ __forceinline__ long long get_t(const void* traw, int i){
    return g_t64 ? ((const long long*)traw)[i] : (long long)((const int*)traw)[i];
}

// ---------------- fused GEMM + exp-sum ----------------
__global__ void __launch_bounds__(256, 2) fce_gemm(const void* __restrict__ traw,
                                                   const float* __restrict__ bias){
    extern __shared__ char smem[];
    uint32_t sb = s2u(smem);
    int tid = threadIdx.x, wid = tid >> 5, lane = tid & 31;
    int gid = lane >> 2, tg = lane & 3;          // groupID, thread-in-group
    int warp_m = wid & 1, warp_n = wid >> 1;     // 2 x 4 warp grid
    int m0 = blockIdx.x * BM;
    int vt = blockIdx.y;
    int v0 = vt * BN;

    if (tid < BN) ((float*)(smem + SM_BIAS))[tid] = bias[v0 + tid];

    const __nv_bfloat16* Ag = g_Xb + (size_t)m0 * HDIM;
    const __nv_bfloat16* Bg = g_Wb + (size_t)v0 * HDIM;

    auto load_stage = [&](int s, int it){
        int k0 = it * BK;
        uint32_t ab = sb + SM_TILES + (uint32_t)s * STG_BYTES + SM_AOFF;
        uint32_t bb = sb + SM_TILES + (uint32_t)s * STG_BYTES + SM_BOFF;
        #pragma unroll
        for (int t = 0; t < 4; t++){
            int id = tid + t*256;
            int row = id >> 3, c = id & 7;
            cp16(ab + swz((uint32_t)(row*128 + c*16)), Ag + (size_t)row*HDIM + k0 + c*8);
        }
        #pragma unroll
        for (int t = 0; t < 4; t++){
            int id = tid + t*256;
            int row = id >> 3, c = id & 7;
            cp16(bb + swz((uint32_t)(row*128 + c*16)), Bg + (size_t)row*HDIM + k0 + c*8);
        }
    };

    load_stage(0, 0);
    asm volatile("cp.async.commit_group;");
    load_stage(1, 1);
    asm volatile("cp.async.commit_group;");

    float c[4][4][4];
    #pragma unroll
    for (int i = 0; i < 4; i++)
        #pragma unroll
        for (int j = 0; j < 4; j++)
            #pragma unroll
            for (int e = 0; e < 4; e++) c[i][j][e] = 0.f;

    for (int it = 0; it < KIT; ++it){
        __syncthreads();                          // all warps done reading stage being overwritten
        if (it + 2 < KIT){
            load_stage((it+2) % NSTG, it+2);
            asm volatile("cp.async.commit_group;");
            asm volatile("cp.async.wait_group 2;");
        } else if (it + 1 < KIT){
            asm volatile("cp.async.wait_group 1;");
        } else {
            asm volatile("cp.async.wait_group 0;");
        }
        __syncthreads();                          // stage `it` visible to all

        int s = it % NSTG;
        uint32_t ab = sb + SM_TILES + (uint32_t)s * STG_BYTES + SM_AOFF;
        uint32_t bb = sb + SM_TILES + (uint32_t)s * STG_BYTES + SM_BOFF;

        #pragma unroll
        for (int k16 = 0; k16 < 4; k16++){
            int kc = k16*16 + ((lane >> 4) << 3);       // + {0,8}
            uint32_t a[4][4];
            #pragma unroll
            for (int mt = 0; mt < 4; mt++){
                int row = warp_m*64 + mt*16 + (lane & 15);
                ldm4(a[mt], ab + swz((uint32_t)(row*128 + kc*2)));
            }
            uint32_t b[4][2];
            #pragma unroll
            for (int np = 0; np < 2; np++){
                int row = warp_n*32 + np*16 + (lane & 7) + (((lane >> 4) & 1) << 3);
                int kb  = k16*16 + (((lane >> 3) & 1) << 3);
                uint32_t r[4];
                ldm4(r, bb + swz((uint32_t)(row*128 + kb*2)));
                b[np*2  ][0] = r[0]; b[np*2  ][1] = r[1];
                b[np*2+1][0] = r[2]; b[np*2+1][1] = r[3];
            }
            #pragma unroll
            for (int mt = 0; mt < 4; mt++)
                #pragma unroll
                for (int nt = 0; nt < 4; nt++)
                    mma16816(c[mt][nt], a[mt], b[nt]);
        }
    }

    // ---- epilogue: bias + exp-sum + target logit, all in registers ----
    const float* sbias = (const float*)(smem + SM_BIAS);
    float* sred = (float*)(smem + SM_RED);

    #pragma unroll
    for (int mt = 0; mt < 4; mt++){
        int r_lo_l = warp_m*64 + mt*16 + gid;      // local row (lo), +8 for hi
        long long tlo = get_t(traw, m0 + r_lo_l);
        long long thi = get_t(traw, m0 + r_lo_l + 8);
        int tl_lo = (int)(tlo - (long long)v0);
        int tl_hi = (int)(thi - (long long)v0);
        float sum_lo = 0.f, sum_hi = 0.f;
        #pragma unroll
        for (int nt = 0; nt < 4; nt++){
            #pragma unroll
            for (int e = 0; e < 2; e++){
                int ln = warp_n*32 + nt*8 + tg*2 + e;
                float bv = sbias[ln];
                float lo = c[mt][nt][e]   + bv;
                float hi = c[mt][nt][2+e] + bv;
                sum_lo += __expf(lo);
                sum_hi += __expf(hi);
                if (ln == tl_lo) g_tgt[m0 + r_lo_l]     = lo;
                if (ln == tl_hi) g_tgt[m0 + r_lo_l + 8] = hi;
            }
        }
        // reduce across the 4 lanes sharing each row (tg = 0..3)
        sum_lo += __shfl_xor_sync(0xFFFFFFFFu, sum_lo, 1);
        sum_lo += __shfl_xor_sync(0xFFFFFFFFu, sum_lo, 2);
        sum_hi += __shfl_xor_sync(0xFFFFFFFFu, sum_hi, 1);
        sum_hi += __shfl_xor_sync(0xFFFFFFFFu, sum_hi, 2);
        if (tg == 0){
            sred[(r_lo_l    ) * 4 + warp_n] = sum_lo;
            sred[(r_lo_l + 8) * 4 + warp_n] = sum_hi;
        }
    }
    __syncthreads();
    if (tid < BM){
        float tot = sred[tid*4] + sred[tid*4+1] + sred[tid*4+2] + sred[tid*4+3];
        g_partial[(size_t)vt * NTOK + m0 + tid] = tot;
    }
}

// ---------------- deterministic reductions ----------------
__global__ void __launch_bounds__(256) row_reduce(const void* __restrict__ traw){
    int n = blockIdx.x*256 + threadIdx.x;
    float s = 0.f;
    for (int p = 0; p < NVT; p++) s += g_partial[(size_t)p * NTOK + n];
    long long t = get_t(traw, n);
    g_nll[n] = (t != -100) ? (logf(s) - g_tgt[n]) : 0.f;
}

__global__ void __launch_bounds__(256) final_red(const void* __restrict__ traw,
                                                 float* __restrict__ out){
    __shared__ float ssum[256];
    __shared__ int   scnt[256];
    int tid = threadIdx.x;
    float s = 0.f; int cn = 0;
    for (int i = tid; i < NTOK; i += 256){
        s += g_nll[i];
        cn += (get_t(traw, i) != -100);
    }
    ssum[tid] = s; scnt[tid] = cn;
    __syncthreads();
    for (int o = 128; o > 0; o >>= 1){
        if (tid < o){ ssum[tid] += ssum[tid+o]; scnt[tid] += scnt[tid+o]; }
        __syncthreads();
    }
    if (tid == 0) out[0] = ssum[0] / (float)scnt[0];
}

// ---------------- launch ----------------
extern "C" void kernel_launch(void* const* d_in, const int* in_sizes, int n_in,
                              void* d_out, int out_size){
    const float* W = nullptr; const float* X = nullptr;
    const void*  T = nullptr; const float* B = nullptr;
    for (int i = 0; i < n_in; i++){
        int s = in_sizes[i];
        if      (s == VOC*HDIM)            W = (const float*)d_in[i];
        else if (s == NTOK*HDIM)           X = (const float*)d_in[i];
        else if (s == NTOK || s == 2*NTOK) T = d_in[i];
        else if (s == VOC)                 B = (const float*)d_in[i];
    }

    void *wb = nullptr, *xb = nullptr;
    cudaGetSymbolAddress(&wb, g_Wb);
    cudaGetSymbolAddress(&xb, g_Xb);

    const int wvec = VOC*HDIM/4;
    const int xvec = NTOK*HDIM/4;
    cvt_bf16<<<(wvec + 255)/256, 256>>>((const float4*)W, (uint2*)wb, wvec);
    cvt_bf16<<<(xvec + 255)/256, 256>>>((const float4*)X, (uint2*)xb, xvec);
    detect_t64<<<1, 32>>>((const unsigned int*)T);

    cudaFuncSetAttribute(fce_gemm, cudaFuncAttributeMaxDynamicSharedMemorySize, SMEM_TOTAL);
    fce_gemm<<<dim3(NTOK/BM, NVT), 256, SMEM_TOTAL>>>(T, B);   // (32, 250)

    row_reduce<<<NTOK/256, 256>>>(T);
    final_red<<<1, 256>>>(T, (float*)d_out);
}